// round 8
// baseline (speedup 1.0000x reference)
#include <cuda_runtime.h>
#include <cuda_bf16.h>
#include <cstdint>
#include <math.h>

// Problem constants
#define PLANE   (2048*2048)       // 4,194,304 pixels per channel plane
#define NBINS   4913              // 17^3 distinct compact keys (289a+17b+c)
#define NFEAT   20

#define K1_BLOCKS  148
#define K1_THREADS 1024
#define K2_THREADS 256
#define K2_WARPS   (K2_THREADS / 32)
#define K2_BLOCKS  ((NBINS + K2_THREADS - 1) / K2_THREADS)   // 20

#define MODE_INT8   0
#define MODE_INT32  1
#define MODE_FP32   2
#define MODE_BF16   3

// ---------------------------------------------------------------------------
// Global scratch. CUDA zeroes __device__ globals at module load. Invariant
// across launches / graph replays: g_hist, g_accum, g_ticket are ZERO on
// entry — kernel 2 re-zeroes everything it consumes. Deterministic:
// integer sums, order-independent.
// ---------------------------------------------------------------------------
__device__ unsigned int g_hist[2 * NBINS];   // [msb bins | lsb bins]
__device__ int          g_accum[NFEAT];
__device__ unsigned int g_ticket;

// ---------------------------------------------------------------------------
// Kernel 1: joint histogram of compact keys for x_in and x_s.
// ATOMS-bound at ~4 lanes/cyc/SM (~14.5us). Ends with fenced flush to g_hist
// and a PDL trigger so the reduce kernel's grid-sync can release early.
// ---------------------------------------------------------------------------
__global__ void __launch_bounds__(K1_THREADS, 1)
hist_kernel(const float* __restrict__ x_in, const float* __restrict__ x_s)
{
    __shared__ unsigned int hm[NBINS];
    __shared__ unsigned int hl[NBINS];

    const int tid = threadIdx.x;
    for (int k = tid; k < NBINS; k += K1_THREADS) { hm[k] = 0u; hl[k] = 0u; }
    __syncthreads();

    const float4* __restrict__ a0 = (const float4*)(x_in);
    const float4* __restrict__ a1 = (const float4*)(x_in + PLANE);
    const float4* __restrict__ a2 = (const float4*)(x_in + 2 * PLANE);
    const float4* __restrict__ b0 = (const float4*)(x_s);
    const float4* __restrict__ b1 = (const float4*)(x_s + PLANE);
    const float4* __restrict__ b2 = (const float4*)(x_s + 2 * PLANE);

    const int NP     = PLANE / 8;                // pairs of float4 positions
    const int stride = K1_BLOCKS * K1_THREADS;

    for (int p = blockIdx.x * K1_THREADS + tid; p < NP; p += stride) {
        const int i0 = 2 * p, i1 = 2 * p + 1;
        // 12 independent streaming loads in flight per thread.
        float4 va0 = __ldcs(&a0[i0]); float4 va1 = __ldcs(&a0[i1]);
        float4 vb0 = __ldcs(&a1[i0]); float4 vb1 = __ldcs(&a1[i1]);
        float4 vc0 = __ldcs(&a2[i0]); float4 vc1 = __ldcs(&a2[i1]);
        float4 wa0 = __ldcs(&b0[i0]); float4 wa1 = __ldcs(&b0[i1]);
        float4 wb0 = __ldcs(&b1[i0]); float4 wb1 = __ldcs(&b1[i1]);
        float4 wc0 = __ldcs(&b2[i0]); float4 wc1 = __ldcs(&b2[i1]);

        // key = 289*a + 17*b + c  (exact in fp32: max 4912 < 2^24)
        atomicAdd(&hm[(int)fmaf(289.f, va0.x, fmaf(17.f, vb0.x, vc0.x))], 1u);
        atomicAdd(&hm[(int)fmaf(289.f, va0.y, fmaf(17.f, vb0.y, vc0.y))], 1u);
        atomicAdd(&hm[(int)fmaf(289.f, va0.z, fmaf(17.f, vb0.z, vc0.z))], 1u);
        atomicAdd(&hm[(int)fmaf(289.f, va0.w, fmaf(17.f, vb0.w, vc0.w))], 1u);
        atomicAdd(&hm[(int)fmaf(289.f, va1.x, fmaf(17.f, vb1.x, vc1.x))], 1u);
        atomicAdd(&hm[(int)fmaf(289.f, va1.y, fmaf(17.f, vb1.y, vc1.y))], 1u);
        atomicAdd(&hm[(int)fmaf(289.f, va1.z, fmaf(17.f, vb1.z, vc1.z))], 1u);
        atomicAdd(&hm[(int)fmaf(289.f, va1.w, fmaf(17.f, vb1.w, vc1.w))], 1u);

        atomicAdd(&hl[(int)fmaf(289.f, wa0.x, fmaf(17.f, wb0.x, wc0.x))], 1u);
        atomicAdd(&hl[(int)fmaf(289.f, wa0.y, fmaf(17.f, wb0.y, wc0.y))], 1u);
        atomicAdd(&hl[(int)fmaf(289.f, wa0.z, fmaf(17.f, wb0.z, wc0.z))], 1u);
        atomicAdd(&hl[(int)fmaf(289.f, wa0.w, fmaf(17.f, wb0.w, wc0.w))], 1u);
        atomicAdd(&hl[(int)fmaf(289.f, wa1.x, fmaf(17.f, wb1.x, wc1.x))], 1u);
        atomicAdd(&hl[(int)fmaf(289.f, wa1.y, fmaf(17.f, wb1.y, wc1.y))], 1u);
        atomicAdd(&hl[(int)fmaf(289.f, wa1.z, fmaf(17.f, wb1.z, wc1.z))], 1u);
        atomicAdd(&hl[(int)fmaf(289.f, wa1.w, fmaf(17.f, wb1.w, wc1.w))], 1u);
    }
    __syncthreads();

    // Flush into single global histogram (REDG, spread addresses).
    for (int k = tid; k < NBINS; k += K1_THREADS) {
        unsigned int vm = hm[k], vl = hl[k];
        if (vm) atomicAdd(&g_hist[k], vm);
        if (vl) atomicAdd(&g_hist[NBINS + k], vl);
    }
    __threadfence();     // flushes visible before the PDL trigger
    __syncthreads();

    // PDL: let the dependent reduce kernel's grid-sync release as soon as
    // every block has flushed (instead of waiting for full kernel drain).
    cudaTriggerProgrammaticLaunchCompletion();
}

// Scalar fallback fetch (only for non-int32 upcast modes; never hot).
__device__ __forceinline__ int fetch_lut(const void* __restrict__ tab, int mode, long long e)
{
    switch (mode) {
        case MODE_FP32:  return (int)((const float*)tab)[e];
        case MODE_BF16:  return (int)__bfloat162float(((const __nv_bfloat16*)tab)[e]);
        default:         return (int)((const signed char*)tab)[e];
    }
}

// ---------------------------------------------------------------------------
// Kernel 2 (reduce + final), launched with Programmatic Stream Serialization:
// starts WHILE kernel 1 drains. Pre-sync: dtype sniff + all LUT loads
// (independent of counts). cudaGridDependencySynchronize(). Post-sync:
// coalesced counts load, 20 MACs, REDUX warp sums, one atomic per feature,
// ticket finish. Consumed state re-zeroed for the next launch.
// All sums fit int32 (|S| <= 2 * 4.2M * 32 ~= 2.7e8 < 2^31).
// ---------------------------------------------------------------------------
__global__ void __launch_bounds__(K2_THREADS)
reduce_final_kernel(const void* __restrict__ msb, const void* __restrict__ lsb,
                    float* __restrict__ out)
{
    __shared__ int s_part[K2_WARPS][NFEAT];
    __shared__ int s_mode;
    __shared__ int s_last;
    const int tid  = threadIdx.x;
    const int wid  = tid >> 5;
    const int lane = tid & 31;

    // ---------- PRE-SYNC (overlaps kernel 1) ----------
    // dtype sniff: warp 0, 8 batched loads per lane
    if (tid < 32) {
        const int* w = (const int*)msb;
        int v[8];
        #pragma unroll
        for (int s = 0; s < 8; s++) v[s] = w[tid + 32 * s];

        bool small = true, flt = true, bfl = true;
        #pragma unroll
        for (int s = 0; s < 8; s++) {
            int x = v[s];
            if (x < -32 || x > 31) small = false;
            float f = __int_as_float(x);
            if (!(isfinite(f) && f == truncf(f) && fabsf(f) <= 32.f)) flt = false;
            unsigned u = (unsigned)x;
            float h0 = __bfloat162float(__ushort_as_bfloat16((unsigned short)(u & 0xFFFFu)));
            float h1 = __bfloat162float(__ushort_as_bfloat16((unsigned short)(u >> 16)));
            if (!(isfinite(h0) && h0 == truncf(h0) && fabsf(h0) <= 32.f &&
                  isfinite(h1) && h1 == truncf(h1) && fabsf(h1) <= 32.f)) bfl = false;
        }
        int m;
        if      (__all_sync(0xffffffffu, small)) m = MODE_INT32;
        else if (__all_sync(0xffffffffu, flt))   m = MODE_FP32;
        else if (__all_sync(0xffffffffu, bfl))   m = MODE_BF16;
        else                                     m = MODE_INT8;
        if (tid == 0) s_mode = m;
    }
    __syncthreads();
    const int mode = s_mode;

    const int j = blockIdx.x * K2_THREADS + tid;
    const bool active = (j < NBINS);

    // LUT rows into registers (independent of counts — fully overlapped)
    int vm[NFEAT], vl[NFEAT];
    if (active) {
        if (mode == MODE_INT32) {
            const int4* rm = (const int4*)((const int*)msb + 320L * j);
            const int4* rl = (const int4*)((const int*)lsb + 320L * j);
            int4 m0 = rm[0], m1 = rm[1], m2 = rm[2], m3 = rm[3], m4 = rm[4];
            int4 l0 = rl[0], l1 = rl[1], l2 = rl[2], l3 = rl[3], l4 = rl[4];
            vm[0]=m0.x; vm[1]=m0.y; vm[2]=m0.z; vm[3]=m0.w;
            vm[4]=m1.x; vm[5]=m1.y; vm[6]=m1.z; vm[7]=m1.w;
            vm[8]=m2.x; vm[9]=m2.y; vm[10]=m2.z; vm[11]=m2.w;
            vm[12]=m3.x; vm[13]=m3.y; vm[14]=m3.z; vm[15]=m3.w;
            vm[16]=m4.x; vm[17]=m4.y; vm[18]=m4.z; vm[19]=m4.w;
            vl[0]=l0.x; vl[1]=l0.y; vl[2]=l0.z; vl[3]=l0.w;
            vl[4]=l1.x; vl[5]=l1.y; vl[6]=l1.z; vl[7]=l1.w;
            vl[8]=l2.x; vl[9]=l2.y; vl[10]=l2.z; vl[11]=l2.w;
            vl[12]=l3.x; vl[13]=l3.y; vl[14]=l3.z; vl[15]=l3.w;
            vl[16]=l4.x; vl[17]=l4.y; vl[18]=l4.z; vl[19]=l4.w;
        } else {
            const long long base = 320LL * j;
            #pragma unroll
            for (int f = 0; f < NFEAT; f++) {
                vm[f] = fetch_lut(msb, mode, base + f);
                vl[f] = fetch_lut(lsb, mode, base + f);
            }
        }
    } else {
        #pragma unroll
        for (int f = 0; f < NFEAT; f++) { vm[f] = 0; vl[f] = 0; }
    }

    // ---------- SYNC: wait for kernel 1's flushed histogram ----------
    cudaGridDependencySynchronize();

    // ---------- POST-SYNC: counts, MAC, reduce, output ----------
    int cm = 0, cl = 0;
    if (active) {
        cm = (int)g_hist[j];
        cl = (int)g_hist[NBINS + j];
        g_hist[j] = 0u;                 // zero-on-consume
        g_hist[NBINS + j] = 0u;
    }

    // Warp-level sums via REDUX; lane f keeps feature f's warp sum.
    int mine = 0;
    #pragma unroll
    for (int f = 0; f < NFEAT; f++) {
        int s = __reduce_add_sync(0xffffffffu, cm * vm[f] + cl * vl[f]);
        if (lane == f) mine = s;
    }
    if (lane < NFEAT) s_part[wid][lane] = mine;
    __syncthreads();

    if (tid < NFEAT) {
        int r = 0;
        #pragma unroll
        for (int w = 0; w < K2_WARPS; w++) r += s_part[w][tid];
        atomicAdd(&g_accum[tid], r);
    }
    __threadfence();
    __syncthreads();

    if (tid == 0) {
        unsigned int t = atomicAdd(&g_ticket, 1u);
        s_last = (t == K2_BLOCKS - 1) ? 1 : 0;
    }
    __syncthreads();

    if (s_last && tid < NFEAT) {
        // Coherent read (L2 atomic), then reset for next launch.
        int S = atomicAdd(&g_accum[tid], 0);
        g_accum[tid] = 0;
        if (tid == 0) g_ticket = 0u;
        // out = clip(round(mean*4)/4, -32, 31.75)
        //     = clamp(rint(S / 2^20), -128, 127) * 0.25   (exact in double)
        double q = rint((double)S / 1048576.0);
        q = fmin(fmax(q, -128.0), 127.0);
        out[tid] = (float)(q * 0.25);
    }
}

// ---------------------------------------------------------------------------
extern "C" void kernel_launch(void* const* d_in, const int* in_sizes, int n_in,
                              void* d_out, int out_size)
{
    const float* x_in = (const float*)d_in[0];
    const float* x_s  = (const float*)d_in[1];
    const void*  msb  = d_in[2];
    const void*  lsb  = d_in[3];
    float*       out  = (float*)d_out;

    hist_kernel<<<K1_BLOCKS, K1_THREADS>>>(x_in, x_s);

    // Launch reduce kernel with Programmatic Stream Serialization so its
    // prologue (dtype sniff + LUT gather) overlaps kernel 1's drain.
    cudaLaunchConfig_t cfg = {};
    cfg.gridDim  = dim3(K2_BLOCKS, 1, 1);
    cfg.blockDim = dim3(K2_THREADS, 1, 1);
    cfg.dynamicSmemBytes = 0;
    cfg.stream = 0;   // same (legacy default) stream as kernel 1
    cudaLaunchAttribute attrs[1];
    attrs[0].id = cudaLaunchAttributeProgrammaticStreamSerialization;
    attrs[0].val.programmaticStreamSerializationAllowed = 1;
    cfg.attrs = attrs;
    cfg.numAttrs = 1;
    cudaLaunchKernelEx(&cfg, reduce_final_kernel, msb, lsb, out);
}